// round 1
// baseline (speedup 1.0000x reference)
#include <cuda_runtime.h>
#include <cstdint>
#include <cstddef>

#define NB      32
#define NTOK    576
#define DIM     1024
#define K_SEL   128
#define CPB     4     // CTAs per batch in greedy
#define RPC     144   // rows per CTA (576/4)

// ---------------- device scratch (static: allocation-free rule) ----------------
__device__ float g_nrm[(size_t)NB * NTOK * DIM];          // 75.5 MB normalized feats
__device__ float g_sim[(size_t)NB * NTOK * NTOK];         // 42.5 MB similarity
__device__ int   g_selint[NB * K_SEL];                    // selected idx (+1), step order
__device__ int   g_sorted[NB * K_SEL];                    // sorted selected idx
__device__ float g_cand_v[NB * 2 * CPB];                  // per-CTA argmax value (double buffered)
__device__ int   g_cand_i[NB * 2 * CPB];                  // per-CTA argmax index
__device__ int   g_done[NB * CPB];                        // monotonic step counters

__device__ __forceinline__ int ld_acq(const int* p) {
    int v;
    asm volatile("ld.acquire.gpu.b32 %0, [%1];" : "=r"(v) : "l"(p) : "memory");
    return v;
}
__device__ __forceinline__ void st_rel(int* p, int v) {
    asm volatile("st.release.gpu.b32 [%0], %1;" :: "l"(p), "r"(v) : "memory");
}
__device__ __forceinline__ float neg_inf() { return __int_as_float(0xff800000); }

// ---------------- kernel 0: reset inter-CTA sync state ----------------
__global__ void init_k() {
    int t = threadIdx.x;
    if (t < NB * CPB) g_done[t] = 0;
}

// ---------------- kernel 1: row L2-normalize (skips CLS token) ----------------
__global__ void norm_k(const float* __restrict__ hs) {
    int n = blockIdx.x, b = blockIdx.y, t = threadIdx.x;  // 256 threads, one float4 each
    const float4* src = (const float4*)(hs + ((size_t)b * (NTOK + 1) + n + 1) * DIM);
    float4 v = src[t];
    float s = v.x * v.x + v.y * v.y + v.z * v.z + v.w * v.w;
    __shared__ float red[8];
    __shared__ float nrm_s;
    #pragma unroll
    for (int o = 16; o; o >>= 1) s += __shfl_xor_sync(0xffffffffu, s, o);
    if ((t & 31) == 0) red[t >> 5] = s;
    __syncthreads();
    if (t == 0) {
        float tot = 0.f;
        #pragma unroll
        for (int w = 0; w < 8; w++) tot += red[w];
        nrm_s = sqrtf(tot);
    }
    __syncthreads();
    float nv = nrm_s;
    float4* dst = (float4*)(g_nrm + ((size_t)b * NTOK + n) * DIM);
    dst[t] = make_float4(v.x / nv, v.y / nv, v.z / nv, v.w / nv);
}

// ---------------- kernel 2: symmetric Gram GEMM, fp32 ----------------
// C[b] = N[b] * N[b]^T, 576x1024. Tiles 64x64, BK=16, 256 thr, 4x4 microtile.
// Only upper-tri tile pairs computed (45 per batch), mirrored on store.
__global__ void gemm_k() {
    int b = blockIdx.y;
    int L = blockIdx.x;
    int i = 0;
    while (L >= 9 - i) { L -= 9 - i; i++; }
    int j = i + L;

    const float* A = g_nrm + (size_t)b * NTOK * DIM;
    __shared__ float As[16][68];
    __shared__ float Bs[16][68];

    int tid = threadIdx.x;
    int tx = tid & 15, ty = tid >> 4;
    int lrow = tid >> 2, lseg = tid & 3;

    float acc[4][4] = {};
    const float* aG = A + (size_t)(i * 64 + lrow) * DIM + lseg * 4;
    const float* bG = A + (size_t)(j * 64 + lrow) * DIM + lseg * 4;

    for (int k0 = 0; k0 < DIM; k0 += 16) {
        float4 av = *(const float4*)(aG + k0);
        float4 bv = *(const float4*)(bG + k0);
        __syncthreads();
        As[lseg * 4 + 0][lrow] = av.x;
        As[lseg * 4 + 1][lrow] = av.y;
        As[lseg * 4 + 2][lrow] = av.z;
        As[lseg * 4 + 3][lrow] = av.w;
        Bs[lseg * 4 + 0][lrow] = bv.x;
        Bs[lseg * 4 + 1][lrow] = bv.y;
        Bs[lseg * 4 + 2][lrow] = bv.z;
        Bs[lseg * 4 + 3][lrow] = bv.w;
        __syncthreads();
        #pragma unroll
        for (int k = 0; k < 16; k++) {
            float4 a = *(const float4*)&As[k][tx * 4];
            float4 bq = *(const float4*)&Bs[k][ty * 4];
            acc[0][0] += a.x * bq.x; acc[0][1] += a.x * bq.y; acc[0][2] += a.x * bq.z; acc[0][3] += a.x * bq.w;
            acc[1][0] += a.y * bq.x; acc[1][1] += a.y * bq.y; acc[1][2] += a.y * bq.z; acc[1][3] += a.y * bq.w;
            acc[2][0] += a.z * bq.x; acc[2][1] += a.z * bq.y; acc[2][2] += a.z * bq.z; acc[2][3] += a.z * bq.w;
            acc[3][0] += a.w * bq.x; acc[3][1] += a.w * bq.y; acc[3][2] += a.w * bq.z; acc[3][3] += a.w * bq.w;
        }
    }

    float* C = g_sim + (size_t)b * NTOK * NTOK;
    int r0 = i * 64 + tx * 4;
    int c0 = j * 64 + ty * 4;
    #pragma unroll
    for (int p = 0; p < 4; p++) {
        *(float4*)&C[(size_t)(r0 + p) * NTOK + c0] =
            make_float4(acc[p][0], acc[p][1], acc[p][2], acc[p][3]);
    }
    // mirrored write (bitwise-identical on diagonal tiles)
    #pragma unroll
    for (int q = 0; q < 4; q++) {
        *(float4*)&C[(size_t)(c0 + q) * NTOK + r0] =
            make_float4(acc[0][q], acc[1][q], acc[2][q], acc[3][q]);
    }
}

// ---------------- kernel 3: greedy SCOPE selection ----------------
// 4 CTAs per batch, 576 threads each; CTA c owns rows [c*144, (c+1)*144).
// Thread (r,p): row m = c*144 + r, column chunk p of 144 (36 float4s from L2).
__global__ void greedy_k(const float* __restrict__ cls_attn,
                         float* __restrict__ idx_out, int write_idx) {
    int b = blockIdx.x >> 2;
    int c = blockIdx.x & 3;
    int t = threadIdx.x;

    __shared__ float cmax[NTOK];
    __shared__ float cls[NTOK];
    __shared__ unsigned char sel[NTOK];
    __shared__ float gains_s[RPC];
    __shared__ int best_s;

    cmax[t] = 0.f;
    cls[t] = cls_attn[b * NTOK + t];
    sel[t] = 0;
    __syncthreads();

    int r = t >> 2, p = t & 3;
    int m = c * RPC + r;
    const float4* rowp = (const float4*)(g_sim + ((size_t)(b * NTOK + m)) * NTOK) + p * 36;
    const float4* cmp4 = ((const float4*)cmax) + p * 36;

    for (int s = 0; s < K_SEL; s++) {
        float acc = 0.f;
        #pragma unroll
        for (int it = 0; it < 36; it++) {
            float4 sv = rowp[it];
            float4 cv = cmp4[it];
            acc += fmaxf(sv.x - cv.x, 0.f);
            acc += fmaxf(sv.y - cv.y, 0.f);
            acc += fmaxf(sv.z - cv.z, 0.f);
            acc += fmaxf(sv.w - cv.w, 0.f);
        }
        acc += __shfl_xor_sync(0xffffffffu, acc, 1);
        acc += __shfl_xor_sync(0xffffffffu, acc, 2);
        if (p == 0) gains_s[r] = sel[m] ? neg_inf() : acc * cls[m];
        __syncthreads();

        if (t < 32) {
            float bv = neg_inf();
            int bi = 0x7fffffff;
            for (int ir = t; ir < RPC; ir += 32) {     // increasing ir: '>' keeps first index
                float v = gains_s[ir];
                if (v > bv) { bv = v; bi = ir; }
            }
            #pragma unroll
            for (int off = 16; off; off >>= 1) {
                float ov = __shfl_down_sync(0xffffffffu, bv, off);
                int   oi = __shfl_down_sync(0xffffffffu, bi, off);
                if (ov > bv || (ov == bv && oi < bi)) { bv = ov; bi = oi; }
            }
            if (t == 0) {
                int slot = (b * 2 + (s & 1)) * CPB + c;
                g_cand_v[slot] = bv;
                g_cand_i[slot] = c * RPC + bi;
                st_rel(&g_done[b * CPB + c], s + 1);
                for (int jj = 0; jj < CPB; jj++)
                    while (ld_acq(&g_done[b * CPB + jj]) < s + 1) {}
                float gbv = neg_inf();
                int gbi = 0x7fffffff;
                for (int jj = 0; jj < CPB; jj++) {
                    int sl = (b * 2 + (s & 1)) * CPB + jj;
                    float v = g_cand_v[sl];
                    int  ix = g_cand_i[sl];
                    if (v > gbv || (v == gbv && ix < gbi)) { gbv = v; gbi = ix; }
                }
                best_s = gbi;
                if (c == 0) {
                    g_selint[b * K_SEL + s] = gbi + 1;
                    if (write_idx) idx_out[b * K_SEL + s] = (float)(gbi + 1);
                }
            }
        }
        __syncthreads();
        int best = best_s;
        if (t == 0) sel[best] = 1;
        cmax[t] = fmaxf(cmax[t], g_sim[((size_t)(b * NTOK) + best) * NTOK + t]);
        __syncthreads();
    }
}

// ---------------- kernel 4: rank-sort the 128 selected indices per batch ----------------
__global__ void sort_k() {
    int b = blockIdx.x, t = threadIdx.x;
    __shared__ int ids[K_SEL];
    ids[t] = g_selint[b * K_SEL + t];
    __syncthreads();
    int v = ids[t];
    int rank = 0;
    for (int j = 0; j < K_SEL; j++) rank += (ids[j] < v);
    g_sorted[b * K_SEL + rank] = v;   // indices unique -> rank is a permutation
}

// ---------------- kernel 5: gather dominant tokens ----------------
__global__ void gather_k(const float* __restrict__ hs, float* __restrict__ out) {
    int k = blockIdx.x, b = blockIdx.y, t = threadIdx.x;  // 256 threads, float4 each
    int src = g_sorted[b * K_SEL + k];
    const float4* sp = (const float4*)(hs + ((size_t)b * (NTOK + 1) + src) * DIM);
    float4* dp = (float4*)(out + ((size_t)b * K_SEL + k) * DIM);
    dp[t] = sp[t];
}

// ---------------- launch ----------------
extern "C" void kernel_launch(void* const* d_in, const int* in_sizes, int n_in,
                              void* d_out, int out_size) {
    const float* hs  = (const float*)d_in[0];   // [32, 577, 1024] f32
    const float* cls = (const float*)d_in[1];   // [32, 576] f32
    float* out = (float*)d_out;

    const int tok_elems = NB * K_SEL * DIM;     // 4,194,304
    int write_idx = (out_size >= tok_elems + NB * K_SEL) ? 1 : 0;
    float* idx_out = out + tok_elems;

    init_k<<<1, 128>>>();
    norm_k<<<dim3(NTOK, NB), 256>>>(hs);
    gemm_k<<<dim3(45, NB), 256>>>();
    greedy_k<<<NB * CPB, NTOK>>>(cls, idx_out, write_idx);
    sort_k<<<NB, K_SEL>>>();
    gather_k<<<dim3(K_SEL, NB), 256>>>(hs, out);
}

// round 3
// speedup vs baseline: 1.1870x; 1.1870x over previous
#include <cuda_runtime.h>
#include <cstdint>
#include <cstddef>

#define NB      32
#define NTOK    576
#define DIM     1024
#define K_SEL   128
#define CPB     4     // CTAs per batch in greedy
#define RPC     144   // rows per CTA (576/4)
#define RPW     8     // rows per warp (144 / 18 warps)

// ---------------- device scratch (static: allocation-free rule) ----------------
__device__ float g_nrm[(size_t)NB * NTOK * DIM];          // 75.5 MB normalized feats
__device__ float g_sim[(size_t)NB * NTOK * NTOK];         // 42.5 MB similarity
__device__ int   g_selint[NB * K_SEL];                    // selected idx (+1), step order
__device__ int   g_sorted[NB * K_SEL];                    // sorted selected idx
__device__ float g_cand_v[NB * 2 * CPB];                  // per-CTA argmax value (double buffered)
__device__ int   g_cand_i[NB * 2 * CPB];                  // per-CTA argmax index
__device__ int   g_done[NB * CPB];                        // monotonic step counters

__device__ __forceinline__ int ld_acq(const int* p) {
    int v;
    asm volatile("ld.acquire.gpu.b32 %0, [%1];" : "=r"(v) : "l"(p) : "memory");
    return v;
}
__device__ __forceinline__ void st_rel(int* p, int v) {
    asm volatile("st.release.gpu.b32 [%0], %1;" :: "l"(p), "r"(v) : "memory");
}
__device__ __forceinline__ float neg_inf() { return __int_as_float(0xff800000); }

// ---------------- kernel 0: reset inter-CTA sync state ----------------
__global__ void init_k() {
    int t = threadIdx.x;
    if (t < NB * CPB) g_done[t] = 0;
}

// ---------------- kernel 1: row L2-normalize (skips CLS token) ----------------
__global__ void norm_k(const float* __restrict__ hs) {
    int n = blockIdx.x, b = blockIdx.y, t = threadIdx.x;  // 256 threads, one float4 each
    const float4* src = (const float4*)(hs + ((size_t)b * (NTOK + 1) + n + 1) * DIM);
    float4 v = src[t];
    float s = v.x * v.x + v.y * v.y + v.z * v.z + v.w * v.w;
    __shared__ float red[8];
    __shared__ float nrm_s;
    #pragma unroll
    for (int o = 16; o; o >>= 1) s += __shfl_xor_sync(0xffffffffu, s, o);
    if ((t & 31) == 0) red[t >> 5] = s;
    __syncthreads();
    if (t == 0) {
        float tot = 0.f;
        #pragma unroll
        for (int w = 0; w < 8; w++) tot += red[w];
        nrm_s = sqrtf(tot);
    }
    __syncthreads();
    float nv = nrm_s;
    float4* dst = (float4*)(g_nrm + ((size_t)b * NTOK + n) * DIM);
    dst[t] = make_float4(v.x / nv, v.y / nv, v.z / nv, v.w / nv);
}

// ---------------- kernel 2: symmetric Gram GEMM, fp32 (unchanged, known-correct) ----------------
__global__ void gemm_k() {
    int b = blockIdx.y;
    int L = blockIdx.x;
    int i = 0;
    while (L >= 9 - i) { L -= 9 - i; i++; }
    int j = i + L;

    const float* A = g_nrm + (size_t)b * NTOK * DIM;
    __shared__ float As[16][68];
    __shared__ float Bs[16][68];

    int tid = threadIdx.x;
    int tx = tid & 15, ty = tid >> 4;
    int lrow = tid >> 2, lseg = tid & 3;

    float acc[4][4] = {};
    const float* aG = A + (size_t)(i * 64 + lrow) * DIM + lseg * 4;
    const float* bG = A + (size_t)(j * 64 + lrow) * DIM + lseg * 4;

    for (int k0 = 0; k0 < DIM; k0 += 16) {
        float4 av = *(const float4*)(aG + k0);
        float4 bv = *(const float4*)(bG + k0);
        __syncthreads();
        As[lseg * 4 + 0][lrow] = av.x;
        As[lseg * 4 + 1][lrow] = av.y;
        As[lseg * 4 + 2][lrow] = av.z;
        As[lseg * 4 + 3][lrow] = av.w;
        Bs[lseg * 4 + 0][lrow] = bv.x;
        Bs[lseg * 4 + 1][lrow] = bv.y;
        Bs[lseg * 4 + 2][lrow] = bv.z;
        Bs[lseg * 4 + 3][lrow] = bv.w;
        __syncthreads();
        #pragma unroll
        for (int k = 0; k < 16; k++) {
            float4 a = *(const float4*)&As[k][tx * 4];
            float4 bq = *(const float4*)&Bs[k][ty * 4];
            acc[0][0] += a.x * bq.x; acc[0][1] += a.x * bq.y; acc[0][2] += a.x * bq.z; acc[0][3] += a.x * bq.w;
            acc[1][0] += a.y * bq.x; acc[1][1] += a.y * bq.y; acc[1][2] += a.y * bq.z; acc[1][3] += a.y * bq.w;
            acc[2][0] += a.z * bq.x; acc[2][1] += a.z * bq.y; acc[2][2] += a.z * bq.z; acc[2][3] += a.z * bq.w;
            acc[3][0] += a.w * bq.x; acc[3][1] += a.w * bq.y; acc[3][2] += a.w * bq.z; acc[3][3] += a.w * bq.w;
        }
    }

    float* C = g_sim + (size_t)b * NTOK * NTOK;
    int r0 = i * 64 + tx * 4;
    int c0 = j * 64 + ty * 4;
    #pragma unroll
    for (int p = 0; p < 4; p++) {
        *(float4*)&C[(size_t)(r0 + p) * NTOK + c0] =
            make_float4(acc[p][0], acc[p][1], acc[p][2], acc[p][3]);
    }
    #pragma unroll
    for (int q = 0; q < 4; q++) {
        *(float4*)&C[(size_t)(c0 + q) * NTOK + r0] =
            make_float4(acc[0][q], acc[1][q], acc[2][q], acc[3][q]);
    }
}

// ---------------- kernel 3: greedy SCOPE selection (coalesced rewrite) ----------------
// 4 CTAs per batch, 576 threads = 18 warps; warp w owns rows [c*144 + w*8, +8).
// Each row is scanned lane-contiguously as 288 float2 (9 iters x 32 lanes):
// every LDG.64 touches exactly 2 cache lines (wavefront floor). cmax chunk is
// loaded once per iter and reused across the warp's 8 rows.
__global__ void greedy_k(const float* __restrict__ cls_attn,
                         float* __restrict__ idx_out, int write_idx) {
    int b = blockIdx.x >> 2;
    int c = blockIdx.x & 3;
    int t = threadIdx.x;
    int w = t >> 5, l = t & 31;

    __shared__ __align__(16) float cmax[NTOK];
    __shared__ float cls[NTOK];
    __shared__ unsigned char sel[NTOK];
    __shared__ float gains_s[RPC];
    __shared__ int best_s;

    cmax[t] = 0.f;
    cls[t] = cls_attn[b * NTOK + t];
    sel[t] = 0;
    __syncthreads();

    int m0 = c * RPC + w * RPW;                       // first row of this warp
    const float2* row2 = (const float2*)(g_sim + ((size_t)(b * NTOK + m0)) * NTOK);
    const float2* cm2 = (const float2*)cmax;

    for (int s = 0; s < K_SEL; s++) {
        float acc[RPW];
        #pragma unroll
        for (int rr = 0; rr < RPW; rr++) acc[rr] = 0.f;

        #pragma unroll
        for (int it = 0; it < 9; it++) {
            int ci = it * 32 + l;                     // float2 column index (0..287)
            float2 cv = cm2[ci];
            #pragma unroll
            for (int rr = 0; rr < RPW; rr++) {
                float2 sv = row2[rr * (NTOK / 2) + ci];
                acc[rr] += fmaxf(sv.x - cv.x, 0.f) + fmaxf(sv.y - cv.y, 0.f);
            }
        }
        #pragma unroll
        for (int rr = 0; rr < RPW; rr++) {
            float a = acc[rr];
            #pragma unroll
            for (int o = 16; o; o >>= 1) a += __shfl_xor_sync(0xffffffffu, a, o);
            acc[rr] = a;
        }
        if (l == 0) {
            #pragma unroll
            for (int rr = 0; rr < RPW; rr++) {
                int lr = w * RPW + rr;
                int m = c * RPC + lr;
                gains_s[lr] = sel[m] ? neg_inf() : acc[rr] * cls[m];
            }
        }
        __syncthreads();

        if (t < 32) {
            float bv = neg_inf();
            int bi = 0x7fffffff;
            for (int ir = t; ir < RPC; ir += 32) {     // increasing ir: '>' keeps first index
                float v = gains_s[ir];
                if (v > bv) { bv = v; bi = ir; }
            }
            #pragma unroll
            for (int off = 16; off; off >>= 1) {
                float ov = __shfl_down_sync(0xffffffffu, bv, off);
                int   oi = __shfl_down_sync(0xffffffffu, bi, off);
                if (ov > bv || (ov == bv && oi < bi)) { bv = ov; bi = oi; }
            }
            if (t == 0) {
                int slot = (b * 2 + (s & 1)) * CPB + c;
                g_cand_v[slot] = bv;
                g_cand_i[slot] = c * RPC + bi;
                st_rel(&g_done[b * CPB + c], s + 1);
                for (int jj = 0; jj < CPB; jj++)
                    while (ld_acq(&g_done[b * CPB + jj]) < s + 1) {}
                float gbv = neg_inf();
                int gbi = 0x7fffffff;
                for (int jj = 0; jj < CPB; jj++) {
                    int sl = (b * 2 + (s & 1)) * CPB + jj;
                    float v = g_cand_v[sl];
                    int  ix = g_cand_i[sl];
                    if (v > gbv || (v == gbv && ix < gbi)) { gbv = v; gbi = ix; }
                }
                best_s = gbi;
                if (c == 0) {
                    g_selint[b * K_SEL + s] = gbi + 1;
                    if (write_idx) idx_out[b * K_SEL + s] = (float)(gbi + 1);
                }
            }
        }
        __syncthreads();
        int best = best_s;
        if (t == 0) sel[best] = 1;
        cmax[t] = fmaxf(cmax[t], g_sim[((size_t)(b * NTOK) + best) * NTOK + t]);
        __syncthreads();
    }
}

// ---------------- kernel 4: rank-sort the 128 selected indices per batch ----------------
__global__ void sort_k() {
    int b = blockIdx.x, t = threadIdx.x;
    __shared__ int ids[K_SEL];
    ids[t] = g_selint[b * K_SEL + t];
    __syncthreads();
    int v = ids[t];
    int rank = 0;
    for (int j = 0; j < K_SEL; j++) rank += (ids[j] < v);
    g_sorted[b * K_SEL + rank] = v;   // indices unique -> rank is a permutation
}

// ---------------- kernel 5: gather dominant tokens ----------------
__global__ void gather_k(const float* __restrict__ hs, float* __restrict__ out) {
    int k = blockIdx.x, b = blockIdx.y, t = threadIdx.x;  // 256 threads, float4 each
    int src = g_sorted[b * K_SEL + k];
    const float4* sp = (const float4*)(hs + ((size_t)b * (NTOK + 1) + src) * DIM);
    float4* dp = (float4*)(out + ((size_t)b * K_SEL + k) * DIM);
    dp[t] = sp[t];
}

// ---------------- launch ----------------
extern "C" void kernel_launch(void* const* d_in, const int* in_sizes, int n_in,
                              void* d_out, int out_size) {
    const float* hs  = (const float*)d_in[0];   // [32, 577, 1024] f32
    const float* cls = (const float*)d_in[1];   // [32, 576] f32
    float* out = (float*)d_out;

    const int tok_elems = NB * K_SEL * DIM;     // 4,194,304
    int write_idx = (out_size >= tok_elems + NB * K_SEL) ? 1 : 0;
    float* idx_out = out + tok_elems;

    init_k<<<1, 128>>>();
    norm_k<<<dim3(NTOK, NB), 256>>>(hs);
    gemm_k<<<dim3(45, NB), 256>>>();
    greedy_k<<<NB * CPB, NTOK>>>(cls, idx_out, write_idx);
    sort_k<<<NB, K_SEL>>>();
    gather_k<<<dim3(K_SEL, NB), 256>>>(hs, out);
}